// round 11
// baseline (speedup 1.0000x reference)
#include <cuda_runtime.h>
#include <math.h>
#include <stdint.h>

// ---------------- problem constants ----------------
#define BATCH 32
#define CH    256
#define HW    1024
#define NPIX  32768
#define NPIXL 32768ULL

// ---------------- static device scratch ----------------
__device__ float g_cold[6400ULL * NPIXL];   // deform im2col (5x5)  839 MB
__device__ float g_osum[256ULL  * NPIXL];   // relu(bn1) += relu(bn3)  [C][NPIX]
__device__ float g_offs[50ULL   * NPIXL];   // offset field [50][NPIX]

// ---------------- PTX helpers ----------------
__device__ __forceinline__ uint32_t smem_u32(const void* p) {
    uint32_t a;
    asm("{ .reg .u64 t; cvta.to.shared.u64 t, %1; cvt.u32.u64 %0, t; }" : "=r"(a) : "l"(p));
    return a;
}
#define CP_ASYNC16(dst, src) \
    asm volatile("cp.async.cg.shared.global [%0], [%1], 16;" :: "r"(dst), "l"(src))
#define CP_COMMIT()  asm volatile("cp.async.commit_group;" ::: "memory")
#define CP_WAIT0()   asm volatile("cp.async.wait_group 0;" ::: "memory")
#define CP_WAIT1()   asm volatile("cp.async.wait_group 1;" ::: "memory")

__device__ __forceinline__ void mma1688(float* c, const uint32_t* a, const uint32_t* b) {
    asm volatile(
        "mma.sync.aligned.m16n8k8.row.col.f32.tf32.tf32.f32 "
        "{%0,%1,%2,%3}, {%4,%5,%6,%7}, {%8,%9}, {%0,%1,%2,%3};"
        : "+f"(c[0]), "+f"(c[1]), "+f"(c[2]), "+f"(c[3])
        : "r"(a[0]), "r"(a[1]), "r"(a[2]), "r"(a[3]), "r"(b[0]), "r"(b[1]));
}
__device__ __forceinline__ void tf32_split(float v, uint32_t& hi, uint32_t& lo) {
    asm("cvt.rna.tf32.f32 %0, %1;" : "=r"(hi) : "f"(v));
    float l = v - __uint_as_float(hi);
    asm("cvt.rna.tf32.f32 %0, %1;" : "=r"(lo) : "f"(l));
}

// ---------------- deformable bilinear sampling ----------------
__global__ void deform_sample_kernel(const float* __restrict__ x)
{
    int b = blockIdx.x;          // 32
    int k = blockIdx.y;          // 25
    int i = k / 5, j = k % 5;
    int tid = threadIdx.x;       // 256
    const float* xb = x + (size_t)b * CH * HW;

    int   offn[4][4];
    float wgt [4][4];
    int   nn  [4];
    #pragma unroll
    for (int q = 0; q < 4; q++) {
        int p  = tid + q * 256;
        int ho = p >> 5, wo = p & 31;
        int n  = (b << 10) + p;
        nn[q]  = n;
        float dy = g_offs[(size_t)(2 * k)     * NPIXL + n];
        float dx = g_offs[(size_t)(2 * k + 1) * NPIXL + n];
        float py = (float)(ho - 2 + i) + dy;
        float px = (float)(wo - 2 + j) + dx;
        float y0 = floorf(py), x0 = floorf(px);
        float wy1 = py - y0, wx1 = px - x0;
        float wy0 = 1.f - wy1, wx0 = 1.f - wx1;
        float ys[2]  = {y0, y0 + 1.f};
        float xs[2]  = {x0, x0 + 1.f};
        float wys[2] = {wy0, wy1};
        float wxs[2] = {wx0, wx1};
        #pragma unroll
        for (int cy = 0; cy < 2; cy++)
            #pragma unroll
            for (int cx = 0; cx < 2; cx++) {
                float yf = ys[cy], xf = xs[cx];
                bool valid = (yf >= 0.f) && (yf <= 31.f) && (xf >= 0.f) && (xf <= 31.f);
                int yc = (int)fminf(fmaxf(yf, 0.f), 31.f);
                int xc = (int)fminf(fmaxf(xf, 0.f), 31.f);
                offn[q][cy * 2 + cx] = yc * 32 + xc;
                wgt [q][cy * 2 + cx] = valid ? wys[cy] * wxs[cx] : 0.f;
            }
    }
    #pragma unroll 2
    for (int c = 0; c < CH; c++) {
        const float* xc = xb + (size_t)c * HW;
        size_t drow = (size_t)(c * 25 + k) * NPIXL;
        #pragma unroll
        for (int q = 0; q < 4; q++) {
            float v = wgt[q][0] * __ldg(&xc[offn[q][0]]) + wgt[q][1] * __ldg(&xc[offn[q][1]])
                    + wgt[q][2] * __ldg(&xc[offn[q][2]]) + wgt[q][3] * __ldg(&xc[offn[q][3]]);
            g_cold[drow + nn[q]] = v;
        }
    }
}

// ---------------- 3xTF32 GEMM, 256 thr, tile 256x128, BK=16 ------------------
// IMPL=0: B explicit [K][NPIX] via cp.async (deform GEMM)
// IMPL=1: B implicit im2col 3x3/pad1 from image (b_cstride/b_bstride in floats)
// A rows: [0,M1) from A1, [M1,M) from A2 (fused offset conv).
// modes: 0 C=relu(bn) (+ A2 rows: C2=acc+bias2)   2 C+=relu(bn)
//        3 out=relu(bn+resid) NCHW
#define BK    16
#define ASROW 264
#define BSROW 136
#define GEMM_SMEM ((2*BK*ASROW + 2*BK*BSROW) * 4)   // 51200 B

template<int IMPL>
__global__ __launch_bounds__(256)
void gemm_mma(const float* __restrict__ A1, const float* __restrict__ A2,
              const float* __restrict__ B, float* __restrict__ C,
              float* __restrict__ C2,
              int M, int M1, int K, int mode,
              const float* __restrict__ gg, const float* __restrict__ bb,
              const float* __restrict__ mm, const float* __restrict__ vv,
              const float* __restrict__ bias2,
              const float* __restrict__ resid, float* __restrict__ outp,
              int b_cstride, int b_bstride)
{
    extern __shared__ float smem[];
    float* as_ = smem;                    // [2][BK][ASROW]
    float* bs_ = smem + 2 * BK * ASROW;   // [2][BK][BSROW]
#define AS(u,k,i) as_[(((u) << 4) + (k)) * ASROW + (i)]
#define BS(u,k,i) bs_[(((u) << 4) + (k)) * BSROW + (i)]

    const int tid  = threadIdx.x;
    const int wid  = tid >> 5;
    const int lane = tid & 31;
    const int lr   = lane >> 2;
    const int lc   = lane & 3;
    const int m0   = blockIdx.y * 256;
    const int n0   = blockIdx.x * 128;
    const int wm   = (wid & 3) * 64;
    const int wn   = (wid >> 2) * 64;
    const bool wact = (m0 + wm) < M;

    float c[4][8][4];
    #pragma unroll
    for (int i = 0; i < 4; i++)
        #pragma unroll
        for (int j = 0; j < 8; j++)
            #pragma unroll
            for (int q = 0; q < 4; q++) c[i][j][q] = 0.f;

    const int nt = K >> 4;

    // ---- A row for this thread ----
    const int am = m0 + tid;
    const float* arow;
    bool aok;
    if (am < M1)      { arow = A1 + (size_t)am * K;        aok = true; }
    else if (am < M)  { arow = A2 + (size_t)(am - M1) * K; aok = true; }
    else              { arow = A1;                         aok = false; }

    float4 ar[4];
    auto loadA = [&](int it) {
        const int kt = it << 4;
        #pragma unroll
        for (int q = 0; q < 4; q++)
            ar[q] = aok ? *reinterpret_cast<const float4*>(&arow[kt + (q << 2)])
                        : make_float4(0.f, 0.f, 0.f, 0.f);
    };
    auto storeA = [&](int buf) {
        #pragma unroll
        for (int q = 0; q < 4; q++) {
            AS(buf, (q << 2) + 0, tid) = ar[q].x;
            AS(buf, (q << 2) + 1, tid) = ar[q].y;
            AS(buf, (q << 2) + 2, tid) = ar[q].z;
            AS(buf, (q << 2) + 3, tid) = ar[q].w;
        }
    };

    // ---- implicit-B state ----
    const int bidx = n0 >> 10;
    const int hob  = (n0 & 1023) >> 5;
    const float* bimg = B + (size_t)bidx * (size_t)b_bstride;
    float br[2][4];
    auto loadBimpl = [&](int it) {
        const int kt = it << 4;
        #pragma unroll
        for (int r = 0; r < 2; r++) {
            int q  = tid + (r << 8);         // 0..511
            int k  = q >> 5;                 // 0..15
            int nq = (q & 31) << 2;          // 0..124
            int kk = kt + k;
            int cc = kk / 9, t = kk % 9;
            int ky = t / 3 - 1, kx = t % 3 - 1;
            int iy = hob + (nq >> 5) + ky;
            int wo = nq & 31;
            const float* srow = bimg + (size_t)cc * b_cstride + iy * 32;
            bool yok = ((unsigned)iy < 32u);
            #pragma unroll
            for (int e = 0; e < 4; e++) {
                int ix = wo + kx + e;
                br[r][e] = (yok && ((unsigned)ix < 32u)) ? __ldg(&srow[ix]) : 0.f;
            }
        }
    };
    auto storeBimpl = [&](int buf) {
        #pragma unroll
        for (int r = 0; r < 2; r++) {
            int q  = tid + (r << 8);
            int k  = q >> 5;
            int nq = (q & 31) << 2;
            *reinterpret_cast<float4*>(&BS(buf, k, nq)) =
                make_float4(br[r][0], br[r][1], br[r][2], br[r][3]);
        }
    };
    auto issueBasync = [&](int it, int buf) {
        const int kt = it << 4;
        #pragma unroll
        for (int r = 0; r < 2; r++) {
            int q   = tid + (r << 8);
            int k   = q >> 5, nf4 = (q & 31) << 2;
            uint32_t dst = smem_u32(&BS(buf, k, nf4));
            const float* src = &B[(size_t)(kt + k) * NPIXL + n0 + nf4];
            CP_ASYNC16(dst, src);
        }
        CP_COMMIT();
    };

    // ---- MMA over one buffer ----
    auto domma = [&](int buf) {
        #pragma unroll
        for (int ks = 0; ks < 2; ks++) {
            const int kb = ks << 3;
            uint32_t ah[4][4], alo[4][4];
            #pragma unroll
            for (int mf = 0; mf < 4; mf++) {
                const int mb = wm + (mf << 4) + lr;
                tf32_split(AS(buf, kb + lc,     mb    ), ah[mf][0], alo[mf][0]);
                tf32_split(AS(buf, kb + lc,     mb + 8), ah[mf][1], alo[mf][1]);
                tf32_split(AS(buf, kb + 4 + lc, mb    ), ah[mf][2], alo[mf][2]);
                tf32_split(AS(buf, kb + 4 + lc, mb + 8), ah[mf][3], alo[mf][3]);
            }
            #pragma unroll
            for (int nf = 0; nf < 8; nf++) {
                const int nb = wn + (nf << 3) + lr;
                uint32_t bh[2], bl[2];
                tf32_split(BS(buf, kb + lc,     nb), bh[0], bl[0]);
                tf32_split(BS(buf, kb + 4 + lc, nb), bh[1], bl[1]);
                #pragma unroll
                for (int mf = 0; mf < 4; mf++) {
                    mma1688(c[mf][nf], ah[mf],  bh);
                    mma1688(c[mf][nf], ah[mf],  bl);
                    mma1688(c[mf][nf], alo[mf], bh);
                }
            }
        }
    };

    if (IMPL == 0) {
        loadA(0); storeA(0);
        issueBasync(0, 0);
        for (int it = 0; it < nt; it++) {
            const int buf = it & 1;
            const bool nxt = (it + 1) < nt;
            if (nxt) { issueBasync(it + 1, buf ^ 1); loadA(it + 1); }
            if (nxt) CP_WAIT1(); else CP_WAIT0();
            __syncthreads();
            if (wact) domma(buf);
            if (nxt) storeA(buf ^ 1);
            __syncthreads();
        }
    } else {
        loadA(0); loadBimpl(0);
        storeA(0); storeBimpl(0);
        __syncthreads();
        for (int it = 0; it < nt; it++) {
            const int buf = it & 1;
            const bool nxt = (it + 1) < nt;
            if (nxt) { loadA(it + 1); loadBimpl(it + 1); }
            if (wact) domma(buf);
            if (nxt) {
                storeA(buf ^ 1); storeBimpl(buf ^ 1);
                __syncthreads();
            }
        }
    }

    // ---------------- epilogue ----------------
    if (wact) {
        #pragma unroll
        for (int mf = 0; mf < 4; mf++) {
            const int r0 = m0 + wm + (mf << 4) + lr;
            const int r1 = r0 + 8;
            float sc0 = 1.f, bi0 = 0.f, sc1 = 1.f, bi1 = 0.f;
            // kind: 0 = bn row, 1 = offset row, 2 = dead
            int k0 = (r0 < M1) ? 0 : (r0 < M ? 1 : 2);
            int k1 = (r1 < M1) ? 0 : (r1 < M ? 1 : 2);
            if (k0 == 0) { float s = gg[r0] * rsqrtf(vv[r0] + 1e-5f); sc0 = s; bi0 = bb[r0] - mm[r0] * s; }
            else if (k0 == 1) bi0 = bias2[r0 - M1];
            if (k1 == 0) { float s = gg[r1] * rsqrtf(vv[r1] + 1e-5f); sc1 = s; bi1 = bb[r1] - mm[r1] * s; }
            else if (k1 == 1) bi1 = bias2[r1 - M1];

            #pragma unroll
            for (int nf = 0; nf < 8; nf++) {
                const int nc = n0 + wn + (nf << 3) + (lc << 1);
                float v0 = c[mf][nf][0] * sc0 + bi0;
                float v1 = c[mf][nf][1] * sc0 + bi0;
                float v2 = c[mf][nf][2] * sc1 + bi1;
                float v3 = c[mf][nf][3] * sc1 + bi1;

                // row 0
                if (k0 == 0) {
                    if (mode == 3) {
                        const int bix = nc >> 10, pix = nc & 1023;
                        size_t o = ((size_t)(bix * CH + r0) << 10) + pix;
                        float2 rs = *reinterpret_cast<const float2*>(&resid[o]);
                        float2 w;
                        w.x = fmaxf(v0 + rs.x, 0.f);
                        w.y = fmaxf(v1 + rs.y, 0.f);
                        *reinterpret_cast<float2*>(&outp[o]) = w;
                    } else if (mode == 2) {
                        size_t o = (size_t)r0 * NPIXL + nc;
                        float2 p = *reinterpret_cast<const float2*>(&C[o]);
                        p.x += fmaxf(v0, 0.f); p.y += fmaxf(v1, 0.f);
                        *reinterpret_cast<float2*>(&C[o]) = p;
                    } else {
                        float2 w; w.x = fmaxf(v0, 0.f); w.y = fmaxf(v1, 0.f);
                        *reinterpret_cast<float2*>(&C[(size_t)r0 * NPIXL + nc]) = w;
                    }
                } else if (k0 == 1) {
                    float2 w; w.x = v0; w.y = v1;
                    *reinterpret_cast<float2*>(&C2[(size_t)(r0 - M1) * NPIXL + nc]) = w;
                }
                // row 1
                if (k1 == 0) {
                    if (mode == 3) {
                        const int bix = nc >> 10, pix = nc & 1023;
                        size_t o = ((size_t)(bix * CH + r1) << 10) + pix;
                        float2 rs = *reinterpret_cast<const float2*>(&resid[o]);
                        float2 w;
                        w.x = fmaxf(v2 + rs.x, 0.f);
                        w.y = fmaxf(v3 + rs.y, 0.f);
                        *reinterpret_cast<float2*>(&outp[o]) = w;
                    } else if (mode == 2) {
                        size_t o = (size_t)r1 * NPIXL + nc;
                        float2 p = *reinterpret_cast<const float2*>(&C[o]);
                        p.x += fmaxf(v2, 0.f); p.y += fmaxf(v3, 0.f);
                        *reinterpret_cast<float2*>(&C[o]) = p;
                    } else {
                        float2 w; w.x = fmaxf(v2, 0.f); w.y = fmaxf(v3, 0.f);
                        *reinterpret_cast<float2*>(&C[(size_t)r1 * NPIXL + nc]) = w;
                    }
                } else if (k1 == 1) {
                    float2 w; w.x = v2; w.y = v3;
                    *reinterpret_cast<float2*>(&C2[(size_t)(r1 - M1) * NPIXL + nc]) = w;
                }
            }
        }
    }
#undef AS
#undef BS
}

// ---------------- host launcher ----------------
extern "C" void kernel_launch(void* const* d_in, const int* in_sizes, int n_in,
                              void* d_out, int out_size)
{
    (void)in_sizes; (void)n_in; (void)out_size;
    const float* x    = (const float*)d_in[0];
    const float* w1   = (const float*)d_in[1];
    const float* woff = (const float*)d_in[2];
    const float* boff = (const float*)d_in[3];
    const float* w3   = (const float*)d_in[4];
    const float* w2   = (const float*)d_in[5];
    const float* g1 = (const float*)d_in[6];  const float* b1 = (const float*)d_in[7];
    const float* m1 = (const float*)d_in[8];  const float* v1 = (const float*)d_in[9];
    const float* g3 = (const float*)d_in[10]; const float* b3 = (const float*)d_in[11];
    const float* m3 = (const float*)d_in[12]; const float* v3 = (const float*)d_in[13];
    const float* g2 = (const float*)d_in[14]; const float* b2 = (const float*)d_in[15];
    const float* m2 = (const float*)d_in[16]; const float* v2 = (const float*)d_in[17];
    float* out = (float*)d_out;

    float *cold, *osum, *offp;
    cudaGetSymbolAddress((void**)&cold, g_cold);
    cudaGetSymbolAddress((void**)&osum, g_osum);
    cudaGetSymbolAddress((void**)&offp, g_offs);

    static int attr_done = 0;
    if (!attr_done) {
        cudaFuncSetAttribute(gemm_mma<0>, cudaFuncAttributeMaxDynamicSharedMemorySize, GEMM_SMEM);
        cudaFuncSetAttribute(gemm_mma<1>, cudaFuncAttributeMaxDynamicSharedMemorySize, GEMM_SMEM);
        attr_done = 1;
    }

    // 1) fused conv1 + offset conv: implicit im2col from x (NCHW)
    //    rows 0..255 -> bn1/relu -> osum ; rows 256..305 -> +bias -> offs
    gemm_mma<1><<<dim3(256, 2), 256, GEMM_SMEM>>>(
        w1, woff, x, osum, offp, 306, 256, 2304, 0,
        g1, b1, m1, v1, boff, nullptr, nullptr, HW, CH * HW);

    // 2) deformable bilinear sampling -> g_cold
    deform_sample_kernel<<<dim3(32, 25), 256>>>(x);

    // 3) deform conv -> bn3 -> relu, accumulate into osum (explicit B)
    gemm_mma<0><<<dim3(256, 1), 256, GEMM_SMEM>>>(
        w3, nullptr, cold, osum, nullptr, 256, 256, 6400, 2,
        g3, b3, m3, v3, nullptr, nullptr, nullptr, 0, 0);

    // 4) conv2: implicit im2col from osum [C][NPIX] -> bn2 + residual -> out
    gemm_mma<1><<<dim3(256, 1), 256, GEMM_SMEM>>>(
        w2, nullptr, osum, nullptr, nullptr, 256, 256, 2304, 3,
        g2, b2, m2, v2, nullptr, x, out, NPIX, HW);
}

// round 12
// speedup vs baseline: 1.5671x; 1.5671x over previous
#include <cuda_runtime.h>
#include <math.h>
#include <stdint.h>

// ---------------- problem constants ----------------
#define BATCH 32
#define CH    256
#define HW    1024
#define NPIX  32768
#define NPIXL 32768ULL

// ---------------- static device scratch ----------------
__device__ float g_col3[2304ULL * NPIXL];   // im2col of x (3x3, pad1)        [K][NPIX]
__device__ float g_col2[2304ULL * NPIXL];   // im2col of osum (3x3, pad1)     [K][NPIX]
__device__ float g_cold[6400ULL * NPIXL];   // deform im2col (5x5)            [K][NPIX]
__device__ float g_osum[256ULL  * NPIXL];   // relu(bn1) += relu(bn3)  [C][NPIX]
__device__ float g_offs[50ULL   * NPIXL];   // offset field [50][NPIX]

// ---------------- PTX helpers ----------------
__device__ __forceinline__ uint32_t smem_u32(const void* p) {
    uint32_t a;
    asm("{ .reg .u64 t; cvta.to.shared.u64 t, %1; cvt.u32.u64 %0, t; }" : "=r"(a) : "l"(p));
    return a;
}
#define CP_ASYNC16(dst, src) \
    asm volatile("cp.async.cg.shared.global [%0], [%1], 16;" :: "r"(dst), "l"(src))
#define CP_COMMIT()  asm volatile("cp.async.commit_group;" ::: "memory")
#define CP_WAIT0()   asm volatile("cp.async.wait_group 0;" ::: "memory")
#define CP_WAIT1()   asm volatile("cp.async.wait_group 1;" ::: "memory")

__device__ __forceinline__ void mma1688(float* c, const uint32_t* a, const uint32_t* b) {
    asm volatile(
        "mma.sync.aligned.m16n8k8.row.col.f32.tf32.tf32.f32 "
        "{%0,%1,%2,%3}, {%4,%5,%6,%7}, {%8,%9}, {%0,%1,%2,%3};"
        : "+f"(c[0]), "+f"(c[1]), "+f"(c[2]), "+f"(c[3])
        : "r"(a[0]), "r"(a[1]), "r"(a[2]), "r"(a[3]), "r"(b[0]), "r"(b[1]));
}
__device__ __forceinline__ void tf32_split(float v, uint32_t& hi, uint32_t& lo) {
    asm("cvt.rna.tf32.f32 %0, %1;" : "=r"(hi) : "f"(v));
    float l = v - __uint_as_float(hi);
    asm("cvt.rna.tf32.f32 %0, %1;" : "=r"(lo) : "f"(l));
}

// ---------------- im2col for 3x3 / pad 1 ----------------
// layout 0: src NCHW x.  layout 1: src [C][NPIX] (channel-major).
__global__ void im2col3_kernel(const float* __restrict__ src,
                               float* __restrict__ dst, int layout)
{
    size_t idx = (size_t)blockIdx.x * blockDim.x + threadIdx.x;
    if (idx >= 2304ULL * NPIXL) return;
    int row = (int)(idx >> 15);
    int n   = (int)(idx & 32767);
    int c = row / 9, t = row % 9;
    int ky = t / 3, kx = t % 3;
    int b = n >> 10, pix = n & 1023;
    int ho = pix >> 5, wo = pix & 31;
    int iy = ho + ky - 1, ix = wo + kx - 1;
    float v = 0.f;
    if ((unsigned)iy < 32u && (unsigned)ix < 32u) {
        size_t s = (layout == 0)
            ? (((size_t)(b * CH + c)) << 10) + (size_t)(iy * 32 + ix)
            : (((size_t)c) << 15) + (size_t)((b << 10) + iy * 32 + ix);
        v = src[s];
    }
    dst[idx] = v;
}

// ---------------- deformable bilinear sampling (4-way channel split) --------
__global__ void deform_sample_kernel(const float* __restrict__ x)
{
    int b = blockIdx.x;          // 32
    int k = blockIdx.y;          // 25
    int cg = blockIdx.z;         // 4 channel groups of 64
    int i = k / 5, j = k % 5;
    int tid = threadIdx.x;       // 256
    const float* xb = x + (size_t)b * CH * HW;

    int   offn[4][4];
    float wgt [4][4];
    int   nn  [4];
    #pragma unroll
    for (int q = 0; q < 4; q++) {
        int p  = tid + q * 256;
        int ho = p >> 5, wo = p & 31;
        int n  = (b << 10) + p;
        nn[q]  = n;
        float dy = g_offs[(size_t)(2 * k)     * NPIXL + n];
        float dx = g_offs[(size_t)(2 * k + 1) * NPIXL + n];
        float py = (float)(ho - 2 + i) + dy;
        float px = (float)(wo - 2 + j) + dx;
        float y0 = floorf(py), x0 = floorf(px);
        float wy1 = py - y0, wx1 = px - x0;
        float wy0 = 1.f - wy1, wx0 = 1.f - wx1;
        float ys[2]  = {y0, y0 + 1.f};
        float xs[2]  = {x0, x0 + 1.f};
        float wys[2] = {wy0, wy1};
        float wxs[2] = {wx0, wx1};
        #pragma unroll
        for (int cy = 0; cy < 2; cy++)
            #pragma unroll
            for (int cx = 0; cx < 2; cx++) {
                float yf = ys[cy], xf = xs[cx];
                bool valid = (yf >= 0.f) && (yf <= 31.f) && (xf >= 0.f) && (xf <= 31.f);
                int yc = (int)fminf(fmaxf(yf, 0.f), 31.f);
                int xc = (int)fminf(fmaxf(xf, 0.f), 31.f);
                offn[q][cy * 2 + cx] = yc * 32 + xc;
                wgt [q][cy * 2 + cx] = valid ? wys[cy] * wxs[cx] : 0.f;
            }
    }
    const int c0 = cg << 6;
    #pragma unroll 2
    for (int cc = 0; cc < 64; cc++) {
        int c = c0 + cc;
        const float* xc = xb + (size_t)c * HW;
        size_t drow = (size_t)(c * 25 + k) * NPIXL;
        #pragma unroll
        for (int q = 0; q < 4; q++) {
            float v = wgt[q][0] * __ldg(&xc[offn[q][0]]) + wgt[q][1] * __ldg(&xc[offn[q][1]])
                    + wgt[q][2] * __ldg(&xc[offn[q][2]]) + wgt[q][3] * __ldg(&xc[offn[q][3]]);
            g_cold[drow + nn[q]] = v;
        }
    }
}

// ---------------- 3xTF32 GEMM, 256 thr, tile 256x128, BK=16, explicit B -----
// A rows: [0,M1) from A1 (bn epilogue), [M1,M) from A2 (bias -> C2).
// modes: 0 C=relu(bn)   2 C+=relu(bn)   3 out=relu(bn+resid) NCHW
#define BK    16
#define ASROW 264
#define BSROW 136
#define GEMM_SMEM ((2*BK*ASROW + 2*BK*BSROW) * 4)   // 51200 B

__global__ __launch_bounds__(256)
void gemm_mma(const float* __restrict__ A1, const float* __restrict__ A2,
              const float* __restrict__ B, float* __restrict__ C,
              float* __restrict__ C2,
              int M, int M1, int K, int mode,
              const float* __restrict__ gg, const float* __restrict__ bb,
              const float* __restrict__ mm, const float* __restrict__ vv,
              const float* __restrict__ bias2,
              const float* __restrict__ resid, float* __restrict__ outp)
{
    extern __shared__ float smem[];
    float* as_ = smem;                    // [2][BK][ASROW]
    float* bs_ = smem + 2 * BK * ASROW;   // [2][BK][BSROW]
#define AS(u,k,i) as_[(((u) << 4) + (k)) * ASROW + (i)]
#define BS(u,k,i) bs_[(((u) << 4) + (k)) * BSROW + (i)]

    const int tid  = threadIdx.x;
    const int wid  = tid >> 5;
    const int lane = tid & 31;
    const int lr   = lane >> 2;
    const int lc   = lane & 3;
    const int m0   = blockIdx.y * 256;
    const int n0   = blockIdx.x * 128;
    const int wm   = (wid & 3) * 64;
    const int wn   = (wid >> 2) * 64;
    const bool wact = (m0 + wm) < M;

    float c[4][8][4];
    #pragma unroll
    for (int i = 0; i < 4; i++)
        #pragma unroll
        for (int j = 0; j < 8; j++)
            #pragma unroll
            for (int q = 0; q < 4; q++) c[i][j][q] = 0.f;

    const int nt = K >> 4;

    // ---- A row for this thread ----
    const int am = m0 + tid;
    const float* arow;
    bool aok;
    if (am < M1)      { arow = A1 + (size_t)am * K;        aok = true; }
    else if (am < M)  { arow = A2 + (size_t)(am - M1) * K; aok = true; }
    else              { arow = A1;                         aok = false; }

    float4 ar[4];
    auto loadA = [&](int it) {
        const int kt = it << 4;
        #pragma unroll
        for (int q = 0; q < 4; q++)
            ar[q] = aok ? *reinterpret_cast<const float4*>(&arow[kt + (q << 2)])
                        : make_float4(0.f, 0.f, 0.f, 0.f);
    };
    auto storeA = [&](int buf) {
        #pragma unroll
        for (int q = 0; q < 4; q++) {
            AS(buf, (q << 2) + 0, tid) = ar[q].x;
            AS(buf, (q << 2) + 1, tid) = ar[q].y;
            AS(buf, (q << 2) + 2, tid) = ar[q].z;
            AS(buf, (q << 2) + 3, tid) = ar[q].w;
        }
    };
    auto issueB = [&](int it, int buf) {
        const int kt = it << 4;
        #pragma unroll
        for (int r = 0; r < 2; r++) {
            int q   = tid + (r << 8);
            int k   = q >> 5, nf4 = (q & 31) << 2;
            uint32_t dst = smem_u32(&BS(buf, k, nf4));
            const float* src = &B[(size_t)(kt + k) * NPIXL + n0 + nf4];
            CP_ASYNC16(dst, src);
        }
        CP_COMMIT();
    };

    auto domma = [&](int buf) {
        #pragma unroll
        for (int ks = 0; ks < 2; ks++) {
            const int kb = ks << 3;
            uint32_t ah[4][4], alo[4][4];
            #pragma unroll
            for (int mf = 0; mf < 4; mf++) {
                const int mb = wm + (mf << 4) + lr;
                tf32_split(AS(buf, kb + lc,     mb    ), ah[mf][0], alo[mf][0]);
                tf32_split(AS(buf, kb + lc,     mb + 8), ah[mf][1], alo[mf][1]);
                tf32_split(AS(buf, kb + 4 + lc, mb    ), ah[mf][2], alo[mf][2]);
                tf32_split(AS(buf, kb + 4 + lc, mb + 8), ah[mf][3], alo[mf][3]);
            }
            #pragma unroll
            for (int nf = 0; nf < 8; nf++) {
                const int nb = wn + (nf << 3) + lr;
                uint32_t bh[2], bl[2];
                tf32_split(BS(buf, kb + lc,     nb), bh[0], bl[0]);
                tf32_split(BS(buf, kb + 4 + lc, nb), bh[1], bl[1]);
                #pragma unroll
                for (int mf = 0; mf < 4; mf++) {
                    mma1688(c[mf][nf], ah[mf],  bh);
                    mma1688(c[mf][nf], ah[mf],  bl);
                    mma1688(c[mf][nf], alo[mf], bh);
                }
            }
        }
    };

    loadA(0); storeA(0);
    issueB(0, 0);
    for (int it = 0; it < nt; it++) {
        const int buf = it & 1;
        const bool nxt = (it + 1) < nt;
        if (nxt) { issueB(it + 1, buf ^ 1); loadA(it + 1); }
        if (nxt) CP_WAIT1(); else CP_WAIT0();
        __syncthreads();
        if (wact) domma(buf);
        if (nxt) storeA(buf ^ 1);
        __syncthreads();
    }

    // ---------------- epilogue ----------------
    if (wact) {
        #pragma unroll
        for (int mf = 0; mf < 4; mf++) {
            const int r0 = m0 + wm + (mf << 4) + lr;
            const int r1 = r0 + 8;
            float sc0 = 1.f, bi0 = 0.f, sc1 = 1.f, bi1 = 0.f;
            int k0 = (r0 < M1) ? 0 : (r0 < M ? 1 : 2);
            int k1 = (r1 < M1) ? 0 : (r1 < M ? 1 : 2);
            if (k0 == 0) { float s = gg[r0] * rsqrtf(vv[r0] + 1e-5f); sc0 = s; bi0 = bb[r0] - mm[r0] * s; }
            else if (k0 == 1) bi0 = bias2[r0 - M1];
            if (k1 == 0) { float s = gg[r1] * rsqrtf(vv[r1] + 1e-5f); sc1 = s; bi1 = bb[r1] - mm[r1] * s; }
            else if (k1 == 1) bi1 = bias2[r1 - M1];

            #pragma unroll
            for (int nf = 0; nf < 8; nf++) {
                const int nc = n0 + wn + (nf << 3) + (lc << 1);
                float v0 = c[mf][nf][0] * sc0 + bi0;
                float v1 = c[mf][nf][1] * sc0 + bi0;
                float v2 = c[mf][nf][2] * sc1 + bi1;
                float v3 = c[mf][nf][3] * sc1 + bi1;

                if (k0 == 0) {
                    if (mode == 3) {
                        const int bix = nc >> 10, pix = nc & 1023;
                        size_t o = ((size_t)(bix * CH + r0) << 10) + pix;
                        float2 rs = *reinterpret_cast<const float2*>(&resid[o]);
                        float2 w;
                        w.x = fmaxf(v0 + rs.x, 0.f);
                        w.y = fmaxf(v1 + rs.y, 0.f);
                        *reinterpret_cast<float2*>(&outp[o]) = w;
                    } else if (mode == 2) {
                        size_t o = (size_t)r0 * NPIXL + nc;
                        float2 p = *reinterpret_cast<const float2*>(&C[o]);
                        p.x += fmaxf(v0, 0.f); p.y += fmaxf(v1, 0.f);
                        *reinterpret_cast<float2*>(&C[o]) = p;
                    } else {
                        float2 w; w.x = fmaxf(v0, 0.f); w.y = fmaxf(v1, 0.f);
                        *reinterpret_cast<float2*>(&C[(size_t)r0 * NPIXL + nc]) = w;
                    }
                } else if (k0 == 1) {
                    float2 w; w.x = v0; w.y = v1;
                    *reinterpret_cast<float2*>(&C2[(size_t)(r0 - M1) * NPIXL + nc]) = w;
                }
                if (k1 == 0) {
                    if (mode == 3) {
                        const int bix = nc >> 10, pix = nc & 1023;
                        size_t o = ((size_t)(bix * CH + r1) << 10) + pix;
                        float2 rs = *reinterpret_cast<const float2*>(&resid[o]);
                        float2 w;
                        w.x = fmaxf(v2 + rs.x, 0.f);
                        w.y = fmaxf(v3 + rs.y, 0.f);
                        *reinterpret_cast<float2*>(&outp[o]) = w;
                    } else if (mode == 2) {
                        size_t o = (size_t)r1 * NPIXL + nc;
                        float2 p = *reinterpret_cast<const float2*>(&C[o]);
                        p.x += fmaxf(v2, 0.f); p.y += fmaxf(v3, 0.f);
                        *reinterpret_cast<float2*>(&C[o]) = p;
                    } else {
                        float2 w; w.x = fmaxf(v2, 0.f); w.y = fmaxf(v3, 0.f);
                        *reinterpret_cast<float2*>(&C[(size_t)r1 * NPIXL + nc]) = w;
                    }
                } else if (k1 == 1) {
                    float2 w; w.x = v2; w.y = v3;
                    *reinterpret_cast<float2*>(&C2[(size_t)(r1 - M1) * NPIXL + nc]) = w;
                }
            }
        }
    }
#undef AS
#undef BS
}

// ---------------- host launcher ----------------
extern "C" void kernel_launch(void* const* d_in, const int* in_sizes, int n_in,
                              void* d_out, int out_size)
{
    (void)in_sizes; (void)n_in; (void)out_size;
    const float* x    = (const float*)d_in[0];
    const float* w1   = (const float*)d_in[1];
    const float* woff = (const float*)d_in[2];
    const float* boff = (const float*)d_in[3];
    const float* w3   = (const float*)d_in[4];
    const float* w2   = (const float*)d_in[5];
    const float* g1 = (const float*)d_in[6];  const float* b1 = (const float*)d_in[7];
    const float* m1 = (const float*)d_in[8];  const float* v1 = (const float*)d_in[9];
    const float* g3 = (const float*)d_in[10]; const float* b3 = (const float*)d_in[11];
    const float* m3 = (const float*)d_in[12]; const float* v3 = (const float*)d_in[13];
    const float* g2 = (const float*)d_in[14]; const float* b2 = (const float*)d_in[15];
    const float* m2 = (const float*)d_in[16]; const float* v2 = (const float*)d_in[17];
    float* out = (float*)d_out;

    float *col3, *col2, *cold, *osum, *offp;
    cudaGetSymbolAddress((void**)&col3, g_col3);
    cudaGetSymbolAddress((void**)&col2, g_col2);
    cudaGetSymbolAddress((void**)&cold, g_cold);
    cudaGetSymbolAddress((void**)&osum, g_osum);
    cudaGetSymbolAddress((void**)&offp, g_offs);

    cudaFuncSetAttribute(gemm_mma, cudaFuncAttributeMaxDynamicSharedMemorySize, GEMM_SMEM);

    const int nblk_i2c = (int)((2304ULL * NPIXL + 255) / 256);

    // 1) im2col of x (shared by conv1 and offset conv)
    im2col3_kernel<<<nblk_i2c, 256>>>(x, col3, 0);

    // 2) fused conv1 + offset conv (explicit B): rows 0..255 -> bn1/relu -> osum,
    //    rows 256..305 -> +bias -> offs
    gemm_mma<<<dim3(256, 2), 256, GEMM_SMEM>>>(
        w1, woff, col3, osum, offp, 306, 256, 2304, 0,
        g1, b1, m1, v1, boff, nullptr, nullptr);

    // 3) deformable bilinear sampling -> g_cold
    deform_sample_kernel<<<dim3(32, 25, 4), 256>>>(x);

    // 4) deform conv -> bn3 -> relu, accumulate into osum (B read ONCE: gridy=1)
    gemm_mma<<<dim3(256, 1), 256, GEMM_SMEM>>>(
        w3, nullptr, cold, osum, nullptr, 256, 256, 6400, 2,
        g3, b3, m3, v3, nullptr, nullptr, nullptr);

    // 5) im2col of osum (channel-major layout)
    im2col3_kernel<<<nblk_i2c, 256>>>(osum, col2, 1);

    // 6) conv2 -> bn2 -> +x residual -> relu -> d_out (B read once)
    gemm_mma<<<dim3(256, 1), 256, GEMM_SMEM>>>(
        w2, nullptr, col2, nullptr, nullptr, 256, 256, 2304, 3,
        g2, b2, m2, v2, nullptr, x, out);
}

// round 15
// speedup vs baseline: 1.7917x; 1.1433x over previous
#include <cuda_runtime.h>
#include <math.h>
#include <stdint.h>

// ---------------- problem constants ----------------
#define BATCH 32
#define CH    256
#define HW    1024
#define NPIX  32768
#define NPIXL 32768ULL

// ---------------- static device scratch ----------------
__device__ float g_col3[2304ULL * NPIXL];   // im2col of x (3x3, pad1)        [K][NPIX]
__device__ float g_col2[2304ULL * NPIXL];   // im2col of osum (3x3, pad1)     [K][NPIX]
__device__ float g_cold[6400ULL * NPIXL];   // deform im2col (5x5)            [K][NPIX]
__device__ float g_osum[256ULL  * NPIXL];   // relu(bn1) += relu(bn3)  [C][NPIX]
__device__ float g_offs[50ULL   * NPIXL];   // offset field [50][NPIX]

// ---------------- PTX helpers ----------------
__device__ __forceinline__ uint32_t smem_u32(const void* p) {
    uint32_t a;
    asm("{ .reg .u64 t; cvta.to.shared.u64 t, %1; cvt.u32.u64 %0, t; }" : "=r"(a) : "l"(p));
    return a;
}
#define CP_ASYNC16(dst, src) \
    asm volatile("cp.async.cg.shared.global [%0], [%1], 16;" :: "r"(dst), "l"(src))
#define CP_COMMIT()  asm volatile("cp.async.commit_group;" ::: "memory")
#define CP_WAIT0()   asm volatile("cp.async.wait_group 0;" ::: "memory")
#define CP_WAIT1()   asm volatile("cp.async.wait_group 1;" ::: "memory")

__device__ __forceinline__ void mma1688(float* c, const uint32_t* a, const uint32_t* b) {
    asm volatile(
        "mma.sync.aligned.m16n8k8.row.col.f32.tf32.tf32.f32 "
        "{%0,%1,%2,%3}, {%4,%5,%6,%7}, {%8,%9}, {%0,%1,%2,%3};"
        : "+f"(c[0]), "+f"(c[1]), "+f"(c[2]), "+f"(c[3])
        : "r"(a[0]), "r"(a[1]), "r"(a[2]), "r"(a[3]), "r"(b[0]), "r"(b[1]));
}
__device__ __forceinline__ void tf32_split(float v, uint32_t& hi, uint32_t& lo) {
    asm("cvt.rna.tf32.f32 %0, %1;" : "=r"(hi) : "f"(v));
    float l = v - __uint_as_float(hi);
    asm("cvt.rna.tf32.f32 %0, %1;" : "=r"(lo) : "f"(l));
}

// ---------------- im2col for 3x3 / pad 1 ----------------
__global__ void im2col3_kernel(const float* __restrict__ src,
                               float* __restrict__ dst, int layout)
{
    size_t idx = (size_t)blockIdx.x * blockDim.x + threadIdx.x;
    if (idx >= 2304ULL * NPIXL) return;
    int row = (int)(idx >> 15);
    int n   = (int)(idx & 32767);
    int c = row / 9, t = row % 9;
    int ky = t / 3, kx = t % 3;
    int b = n >> 10, pix = n & 1023;
    int ho = pix >> 5, wo = pix & 31;
    int iy = ho + ky - 1, ix = wo + kx - 1;
    float v = 0.f;
    if ((unsigned)iy < 32u && (unsigned)ix < 32u) {
        size_t s = (layout == 0)
            ? (((size_t)(b * CH + c)) << 10) + (size_t)(iy * 32 + ix)
            : (((size_t)c) << 15) + (size_t)((b << 10) + iy * 32 + ix);
        v = src[s];
    }
    dst[idx] = v;
}

// ---------------- deformable bilinear sampling (4-way channel split) --------
__global__ void deform_sample_kernel(const float* __restrict__ x)
{
    int b = blockIdx.x;          // 32
    int k = blockIdx.y;          // 25
    int cg = blockIdx.z;         // 4 channel groups of 64
    int i = k / 5, j = k % 5;
    int tid = threadIdx.x;       // 256
    const float* xb = x + (size_t)b * CH * HW;

    int   offn[4][4];
    float wgt [4][4];
    int   nn  [4];
    #pragma unroll
    for (int q = 0; q < 4; q++) {
        int p  = tid + q * 256;
        int ho = p >> 5, wo = p & 31;
        int n  = (b << 10) + p;
        nn[q]  = n;
        float dy = g_offs[(size_t)(2 * k)     * NPIXL + n];
        float dx = g_offs[(size_t)(2 * k + 1) * NPIXL + n];
        float py = (float)(ho - 2 + i) + dy;
        float px = (float)(wo - 2 + j) + dx;
        float y0 = floorf(py), x0 = floorf(px);
        float wy1 = py - y0, wx1 = px - x0;
        float wy0 = 1.f - wy1, wx0 = 1.f - wx1;
        float ys[2]  = {y0, y0 + 1.f};
        float xs[2]  = {x0, x0 + 1.f};
        float wys[2] = {wy0, wy1};
        float wxs[2] = {wx0, wx1};
        #pragma unroll
        for (int cy = 0; cy < 2; cy++)
            #pragma unroll
            for (int cx = 0; cx < 2; cx++) {
                float yf = ys[cy], xf = xs[cx];
                bool valid = (yf >= 0.f) && (yf <= 31.f) && (xf >= 0.f) && (xf <= 31.f);
                int yc = (int)fminf(fmaxf(yf, 0.f), 31.f);
                int xc = (int)fminf(fmaxf(xf, 0.f), 31.f);
                offn[q][cy * 2 + cx] = yc * 32 + xc;
                wgt [q][cy * 2 + cx] = valid ? wys[cy] * wxs[cx] : 0.f;
            }
    }
    const int c0 = cg << 6;
    #pragma unroll 2
    for (int cc = 0; cc < 64; cc++) {
        int c = c0 + cc;
        const float* xc = xb + (size_t)c * HW;
        size_t drow = (size_t)(c * 25 + k) * NPIXL;
        #pragma unroll
        for (int q = 0; q < 4; q++) {
            float v = wgt[q][0] * __ldg(&xc[offn[q][0]]) + wgt[q][1] * __ldg(&xc[offn[q][1]])
                    + wgt[q][2] * __ldg(&xc[offn[q][2]]) + wgt[q][3] * __ldg(&xc[offn[q][3]]);
            g_cold[drow + nn[q]] = v;
        }
    }
}

// ---------------- 3xTF32 mma.sync GEMM (R8 structure + 3-pass ordering) -----
// Block 128x128, 4 warps, warp tile 64x64, BK=16, cp.async double-buffered B.
// modes: 0 C=relu(bn)   1 C=acc+bias   2 C+=relu(bn)   3 out=relu(bn+resid) NCHW
#define BK 16
#define SROW 136

__global__ __launch_bounds__(128)
void gemm_mma(const float* __restrict__ A, const float* __restrict__ B,
              float* __restrict__ C, int M, int K, int mode,
              const float* __restrict__ gg, const float* __restrict__ bb,
              const float* __restrict__ mm, const float* __restrict__ vv,
              const float* __restrict__ resid, float* __restrict__ outp)
{
    __shared__ float As[2][BK][SROW];
    __shared__ float Bs[2][BK][SROW];

    const int tid  = threadIdx.x;
    const int wid  = tid >> 5;
    const int lane = tid & 31;
    const int lr   = lane >> 2;
    const int lc   = lane & 3;
    const int m0   = blockIdx.y * 128;
    const int n0   = blockIdx.x * 128;
    const int wm   = (wid & 1) * 64;
    const int wn   = (wid >> 1) * 64;

    float c[4][8][4];
    #pragma unroll
    for (int i = 0; i < 4; i++)
        #pragma unroll
        for (int j = 0; j < 8; j++)
            #pragma unroll
            for (int q = 0; q < 4; q++) c[i][j][q] = 0.f;

    const int nt = K >> 4;
    const int am = m0 + tid;
    const bool aok = (am < M);
    const float* arow = A + (size_t)(aok ? am : 0) * K;

    auto issueB = [&](int it, int buf) {
        const int kt = it << 4;
        #pragma unroll
        for (int q = 0; q < 4; q++) {
            int f   = tid + (q << 7);
            int k   = f >> 5, nf4 = (f & 31) << 2;
            uint32_t dst = smem_u32(&Bs[buf][k][nf4]);
            const float* src = &B[(size_t)(kt + k) * NPIXL + n0 + nf4];
            CP_ASYNC16(dst, src);
        }
        CP_COMMIT();
    };
    float4 ar[4];
    auto loadA = [&](int it) {
        const int kt = it << 4;
        #pragma unroll
        for (int q = 0; q < 4; q++)
            ar[q] = aok ? *reinterpret_cast<const float4*>(&arow[kt + (q << 2)])
                        : make_float4(0.f, 0.f, 0.f, 0.f);
    };
    auto storeA = [&](int buf) {
        #pragma unroll
        for (int q = 0; q < 4; q++) {
            As[buf][(q << 2) + 0][tid] = ar[q].x;
            As[buf][(q << 2) + 1][tid] = ar[q].y;
            As[buf][(q << 2) + 2][tid] = ar[q].z;
            As[buf][(q << 2) + 3][tid] = ar[q].w;
        }
    };

    loadA(0); storeA(0);
    issueB(0, 0);

    for (int it = 0; it < nt; it++) {
        const int buf = it & 1;
        const bool nxt = (it + 1) < nt;
        if (nxt) { issueB(it + 1, buf ^ 1); loadA(it + 1); }
        if (nxt) CP_WAIT1(); else CP_WAIT0();
        __syncthreads();

        #pragma unroll
        for (int ks = 0; ks < 2; ks++) {
            const int kb = ks << 3;
            uint32_t ah[4][4], alo[4][4], bh[8][2], bl[8][2];
            #pragma unroll
            for (int mf = 0; mf < 4; mf++) {
                const int mb = wm + (mf << 4) + lr;
                tf32_split(As[buf][kb + lc    ][mb    ], ah[mf][0], alo[mf][0]);
                tf32_split(As[buf][kb + lc    ][mb + 8], ah[mf][1], alo[mf][1]);
                tf32_split(As[buf][kb + 4 + lc][mb    ], ah[mf][2], alo[mf][2]);
                tf32_split(As[buf][kb + 4 + lc][mb + 8], ah[mf][3], alo[mf][3]);
            }
            #pragma unroll
            for (int nf = 0; nf < 8; nf++) {
                const int nb = wn + (nf << 3) + lr;
                tf32_split(Bs[buf][kb + lc    ][nb], bh[nf][0], bl[nf][0]);
                tf32_split(Bs[buf][kb + 4 + lc][nb], bh[nf][1], bl[nf][1]);
            }
            // 3 passes: each accumulator touched once per pass ->
            // dependent-HMMA distance 32 instead of 1.
            #pragma unroll
            for (int nf = 0; nf < 8; nf++)
                #pragma unroll
                for (int mf = 0; mf < 4; mf++)
                    mma1688(c[mf][nf], ah[mf], bh[nf]);
            #pragma unroll
            for (int nf = 0; nf < 8; nf++)
                #pragma unroll
                for (int mf = 0; mf < 4; mf++)
                    mma1688(c[mf][nf], ah[mf], bl[nf]);
            #pragma unroll
            for (int nf = 0; nf < 8; nf++)
                #pragma unroll
                for (int mf = 0; mf < 4; mf++)
                    mma1688(c[mf][nf], alo[mf], bh[nf]);
        }
        if (nxt) storeA(buf ^ 1);
        __syncthreads();
    }

    // ---------------- epilogue ----------------
    #pragma unroll
    for (int mf = 0; mf < 4; mf++) {
        const int r0 = m0 + wm + (mf << 4) + lr;
        const int r1 = r0 + 8;
        float sc0 = 1.f, bi0 = 0.f, sc1 = 1.f, bi1 = 0.f;
        if (mode == 1) {
            if (r0 < M) bi0 = bb[r0];
            if (r1 < M) bi1 = bb[r1];
        } else {
            float s0 = gg[r0] * rsqrtf(vv[r0] + 1e-5f);
            float s1 = gg[r1] * rsqrtf(vv[r1] + 1e-5f);
            sc0 = s0; bi0 = bb[r0] - mm[r0] * s0;
            sc1 = s1; bi1 = bb[r1] - mm[r1] * s1;
        }
        #pragma unroll
        for (int nf = 0; nf < 8; nf++) {
            const int nc = n0 + wn + (nf << 3) + (lc << 1);
            float v0 = c[mf][nf][0] * sc0 + bi0;
            float v1 = c[mf][nf][1] * sc0 + bi0;
            float v2 = c[mf][nf][2] * sc1 + bi1;
            float v3 = c[mf][nf][3] * sc1 + bi1;
            if (mode == 0 || mode == 2) {
                v0 = fmaxf(v0, 0.f); v1 = fmaxf(v1, 0.f);
                v2 = fmaxf(v2, 0.f); v3 = fmaxf(v3, 0.f);
            }
            if (mode == 3) {
                const int bidx = n0 >> 10;
                const int pix  = nc & 1023;
                if (r0 < M) {
                    size_t o = ((size_t)(bidx * CH + r0) << 10) + pix;
                    float2 rs = *reinterpret_cast<const float2*>(&resid[o]);
                    float2 w;
                    w.x = fmaxf(v0 + rs.x, 0.f);
                    w.y = fmaxf(v1 + rs.y, 0.f);
                    *reinterpret_cast<float2*>(&outp[o]) = w;
                }
                if (r1 < M) {
                    size_t o = ((size_t)(bidx * CH + r1) << 10) + pix;
                    float2 rs = *reinterpret_cast<const float2*>(&resid[o]);
                    float2 w;
                    w.x = fmaxf(v2 + rs.x, 0.f);
                    w.y = fmaxf(v3 + rs.y, 0.f);
                    *reinterpret_cast<float2*>(&outp[o]) = w;
                }
            } else if (mode == 2) {
                if (r0 < M) {
                    size_t o = (size_t)r0 * NPIXL + nc;
                    float2 p = *reinterpret_cast<const float2*>(&C[o]);
                    p.x += v0; p.y += v1;
                    *reinterpret_cast<float2*>(&C[o]) = p;
                }
                if (r1 < M) {
                    size_t o = (size_t)r1 * NPIXL + nc;
                    float2 p = *reinterpret_cast<const float2*>(&C[o]);
                    p.x += v2; p.y += v3;
                    *reinterpret_cast<float2*>(&C[o]) = p;
                }
            } else {
                if (r0 < M) {
                    float2 w; w.x = v0; w.y = v1;
                    *reinterpret_cast<float2*>(&C[(size_t)r0 * NPIXL + nc]) = w;
                }
                if (r1 < M) {
                    float2 w; w.x = v2; w.y = v3;
                    *reinterpret_cast<float2*>(&C[(size_t)r1 * NPIXL + nc]) = w;
                }
            }
        }
    }
}

// ---------------- host launcher ----------------
extern "C" void kernel_launch(void* const* d_in, const int* in_sizes, int n_in,
                              void* d_out, int out_size)
{
    (void)in_sizes; (void)n_in; (void)out_size;
    const float* x    = (const float*)d_in[0];
    const float* w1   = (const float*)d_in[1];
    const float* woff = (const float*)d_in[2];
    const float* boff = (const float*)d_in[3];
    const float* w3   = (const float*)d_in[4];
    const float* w2   = (const float*)d_in[5];
    const float* g1 = (const float*)d_in[6];  const float* b1 = (const float*)d_in[7];
    const float* m1 = (const float*)d_in[8];  const float* v1 = (const float*)d_in[9];
    const float* g3 = (const float*)d_in[10]; const float* b3 = (const float*)d_in[11];
    const float* m3 = (const float*)d_in[12]; const float* v3 = (const float*)d_in[13];
    const float* g2 = (const float*)d_in[14]; const float* b2 = (const float*)d_in[15];
    const float* m2 = (const float*)d_in[16]; const float* v2 = (const float*)d_in[17];
    float* out = (float*)d_out;

    float *col3, *col2, *cold, *osum, *offp;
    cudaGetSymbolAddress((void**)&col3, g_col3);
    cudaGetSymbolAddress((void**)&col2, g_col2);
    cudaGetSymbolAddress((void**)&cold, g_cold);
    cudaGetSymbolAddress((void**)&osum, g_osum);
    cudaGetSymbolAddress((void**)&offp, g_offs);

    const int nblk_i2c = (int)((2304ULL * NPIXL + 255) / 256);

    // 1) im2col of x (shared by conv1 and offset conv)
    im2col3_kernel<<<nblk_i2c, 256>>>(x, col3, 0);

    // 2) conv1 -> bn1 -> relu  into g_osum
    gemm_mma<<<dim3(256, 2), 128>>>(w1, col3, osum, 256, 2304, 0,
                                    g1, b1, m1, v1, nullptr, nullptr);

    // 3) offset conv (+ bias) into g_offs
    gemm_mma<<<dim3(256, 1), 128>>>(woff, col3, offp, 50, 2304, 1,
                                    nullptr, boff, nullptr, nullptr, nullptr, nullptr);

    // 4) deformable bilinear sampling -> g_cold
    deform_sample_kernel<<<dim3(32, 25, 4), 256>>>(x);

    // 5) deform conv -> bn3 -> relu, accumulate into g_osum
    gemm_mma<<<dim3(256, 2), 128>>>(w3, cold, osum, 256, 6400, 2,
                                    g3, b3, m3, v3, nullptr, nullptr);

    // 6) im2col of g_osum (channel-major layout)
    im2col3_kernel<<<nblk_i2c, 256>>>(osum, col2, 1);

    // 7) conv2 -> bn2 -> +x residual -> relu -> d_out (NCHW)
    gemm_mma<<<dim3(256, 2), 128>>>(w2, col2, nullptr, 256, 2304, 3,
                                    g2, b2, m2, v2, x, out);
}